// round 9
// baseline (speedup 1.0000x reference)
#include <cuda_runtime.h>
#include <cstdint>

#define N_ROWS   16384
#define DMODEL   768
#define DLATENT  12288
#define TOPK     20
#define KSEL     32                  // refined candidate count
#define POOLN    1024                // captured candidates cap per row
#define KINT     (DMODEL / 4)        // 192 packed int32 per row
#define CAPTHR   2.0f                // capture threshold (32nd stat ~2.79)

// ---- scratch (no allocation allowed -> __device__ globals) ----
__device__ float g_WdecT[(size_t)DLATENT * DMODEL];  // 37.7 MB
__device__ int   g_Xq[(size_t)N_ROWS * KINT];        // 12.6 MB
__device__ int   g_Wq[(size_t)DLATENT * KINT];       // 9.4 MB
__device__ float g_sx[N_ROWS];
__device__ float g_sw[DLATENT];
__device__ int   g_pcnt[N_ROWS];
__device__ float g_poolv[(size_t)N_ROWS * POOLN];    // 64 MB
__device__ int   g_pooli[(size_t)N_ROWS * POOLN];    // 64 MB

__global__ void zero_pcnt() {
    int i = blockIdx.x * 256 + threadIdx.x;
    if (i < N_ROWS) g_pcnt[i] = 0;
}

// ============================================================
// Kernel Q: per-row symmetric int8 quantization (coalesced, R7 form)
// ============================================================
__global__ __launch_bounds__(192)
void quant_kernel(const float* __restrict__ src, int* __restrict__ dstq,
                  float* __restrict__ dscale) {
    const int row = blockIdx.x;
    const int t   = threadIdx.x;          // 0..191
    float4 v = *(const float4*)(src + (size_t)row * DMODEL + t * 4);
    float m = fmaxf(fmaxf(fabsf(v.x), fabsf(v.y)), fmaxf(fabsf(v.z), fabsf(v.w)));

    #pragma unroll
    for (int off = 16; off > 0; off >>= 1)
        m = fmaxf(m, __shfl_xor_sync(0xffffffffu, m, off));
    __shared__ float wm[6];
    __shared__ float smax;
    if ((t & 31) == 0) wm[t >> 5] = m;
    __syncthreads();
    if (t == 0) {
        float mm = wm[0];
        #pragma unroll
        for (int q = 1; q < 6; ++q) mm = fmaxf(mm, wm[q]);
        smax = mm;
        dscale[row] = mm / 127.0f;
    }
    __syncthreads();

    float inv = (smax > 0.f) ? 127.0f / smax : 0.f;
    int q0 = __float2int_rn(v.x * inv);
    int q1 = __float2int_rn(v.y * inv);
    int q2 = __float2int_rn(v.z * inv);
    int q3 = __float2int_rn(v.w * inv);
    dstq[(size_t)row * KINT + t] =
        (q0 & 0xFF) | ((q1 & 0xFF) << 8) | ((q2 & 0xFF) << 16) | (q3 << 24);
}

// ============================================================
// Kernel 0: transpose W_dec [768,12288] -> W_decT [12288,768]
// ============================================================
__global__ void transpose_wdec(const float* __restrict__ Wdec) {
    __shared__ float tile[32][33];
    int l0 = blockIdx.x * 32;
    int d0 = blockIdx.y * 32;
    int tx = threadIdx.x, ty = threadIdx.y;
    #pragma unroll
    for (int r = 0; r < 32; r += 8)
        tile[ty + r][tx] = Wdec[(size_t)(d0 + ty + r) * DLATENT + l0 + tx];
    __syncthreads();
    #pragma unroll
    for (int r = 0; r < 32; r += 8)
        g_WdecT[(size_t)(l0 + ty + r) * DMODEL + d0 + tx] = tile[tx][ty + r];
}

// ============================================================
// Kernel 1: int8 dp4a encode GEMM (R7 mainloop verbatim) with
// fused threshold capture epilogue (no latent materialization).
// ============================================================
#define IBM 128
#define IBN 128
#define IBK 16
#define NKT (KINT / IBK)             // 12

__global__ __launch_bounds__(256)
void encode_gemm_i8(const float* __restrict__ benc) {
    __shared__ int As[2][IBK][IBM];
    __shared__ int Bs[2][IBK][IBN];

    const int t  = threadIdx.x;
    const int bn = blockIdx.x;
    const int bm = blockIdx.y;
    const int tm = t >> 4;
    const int tn = t & 15;

    const int* Ag = g_Xq + (size_t)(bm * IBM) * KINT;
    const int* Bg = g_Wq + (size_t)(bn * IBN) * KINT;

    const int r0 = t >> 2, c0 = (t & 3) * 4;
    const int r1 = (t + 256) >> 2;

    int acc[8][8];
    #pragma unroll
    for (int i = 0; i < 8; ++i)
        #pragma unroll
        for (int j = 0; j < 8; ++j) acc[i][j] = 0;

    {
        int4 a0 = *(const int4*)(Ag + (size_t)r0 * KINT + c0);
        int4 a1 = *(const int4*)(Ag + (size_t)r1 * KINT + c0);
        int4 b0 = *(const int4*)(Bg + (size_t)r0 * KINT + c0);
        int4 b1 = *(const int4*)(Bg + (size_t)r1 * KINT + c0);
        As[0][c0    ][r0] = a0.x; As[0][c0 + 1][r0] = a0.y;
        As[0][c0 + 2][r0] = a0.z; As[0][c0 + 3][r0] = a0.w;
        As[0][c0    ][r1] = a1.x; As[0][c0 + 1][r1] = a1.y;
        As[0][c0 + 2][r1] = a1.z; As[0][c0 + 3][r1] = a1.w;
        Bs[0][c0    ][r0] = b0.x; Bs[0][c0 + 1][r0] = b0.y;
        Bs[0][c0 + 2][r0] = b0.z; Bs[0][c0 + 3][r0] = b0.w;
        Bs[0][c0    ][r1] = b1.x; Bs[0][c0 + 1][r1] = b1.y;
        Bs[0][c0 + 2][r1] = b1.z; Bs[0][c0 + 3][r1] = b1.w;
    }
    __syncthreads();

    int buf = 0;
    for (int kt = 0; kt < NKT; ++kt) {
        int4 pa0, pa1, pb0, pb1;
        if (kt + 1 < NKT) {
            const int koff = (kt + 1) * IBK + c0;
            pa0 = *(const int4*)(Ag + (size_t)r0 * KINT + koff);
            pa1 = *(const int4*)(Ag + (size_t)r1 * KINT + koff);
            pb0 = *(const int4*)(Bg + (size_t)r0 * KINT + koff);
            pb1 = *(const int4*)(Bg + (size_t)r1 * KINT + koff);
        }

        #pragma unroll
        for (int kk = 0; kk < IBK; ++kk) {
            int a[8], b[8];
            *(int4*)(a)     = *(const int4*)&As[buf][kk][tm * 8];
            *(int4*)(a + 4) = *(const int4*)&As[buf][kk][tm * 8 + 4];
            *(int4*)(b)     = *(const int4*)&Bs[buf][kk][tn * 8];
            *(int4*)(b + 4) = *(const int4*)&Bs[buf][kk][tn * 8 + 4];
            #pragma unroll
            for (int i = 0; i < 8; ++i)
                #pragma unroll
                for (int j = 0; j < 8; ++j)
                    acc[i][j] = __dp4a(a[i], b[j], acc[i][j]);
        }

        if (kt + 1 < NKT) {
            int nb = buf ^ 1;
            As[nb][c0    ][r0] = pa0.x; As[nb][c0 + 1][r0] = pa0.y;
            As[nb][c0 + 2][r0] = pa0.z; As[nb][c0 + 3][r0] = pa0.w;
            As[nb][c0    ][r1] = pa1.x; As[nb][c0 + 1][r1] = pa1.y;
            As[nb][c0 + 2][r1] = pa1.z; As[nb][c0 + 3][r1] = pa1.w;
            Bs[nb][c0    ][r0] = pb0.x; Bs[nb][c0 + 1][r0] = pb0.y;
            Bs[nb][c0 + 2][r0] = pb0.z; Bs[nb][c0 + 3][r0] = pb0.w;
            Bs[nb][c0    ][r1] = pb1.x; Bs[nb][c0 + 1][r1] = pb1.y;
            Bs[nb][c0 + 2][r1] = pb1.z; Bs[nb][c0 + 3][r1] = pb1.w;
            __syncthreads();
            buf = nb;
        }
    }

    // epilogue: scale + bias, capture values above CAPTHR into per-row pool
    const int gcol = bn * IBN + tn * 8;
    float sw_[8], bias[8];
    #pragma unroll
    for (int j = 0; j < 8; ++j) {
        sw_[j]  = g_sw[gcol + j];
        bias[j] = __ldg(&benc[gcol + j]);
    }
    #pragma unroll
    for (int i = 0; i < 8; ++i) {
        const int grow = bm * IBM + tm * 8 + i;
        const float s = g_sx[grow];
        #pragma unroll
        for (int j = 0; j < 8; ++j) {
            float v = (float)acc[i][j] * s * sw_[j] + bias[j];
            if (v > CAPTHR) {
                int p = atomicAdd(&g_pcnt[grow], 1);
                if (p < POOLN) {
                    g_poolv[(size_t)grow * POOLN + p] = v;
                    g_pooli[(size_t)grow * POOLN + p] = gcol + j;
                }
            }
        }
    }
}

// ============================================================
// Kernel 2 (fused tail): per row —
//   a) rank-select approx top-32 from captured pool (O(n^2) smem)
//   b) fp64 refine: exact latents for the 32, exact top-20
//   c) decode: out = b_dec + sum_k v_k * W_decT[idx_k]
// ============================================================
__global__ __launch_bounds__(256)
void tail_kernel(const float* __restrict__ X,
                 const float* __restrict__ W,
                 const float* __restrict__ benc,
                 const float* __restrict__ bdec,
                 float* __restrict__ out) {
    const int row  = blockIdx.x;
    const int t    = threadIdx.x;    // 256
    const int w    = t >> 5;
    const int lane = t & 31;

    __shared__ float  pv[POOLN];
    __shared__ int    pc[POOLN];
    __shared__ float  xs[DMODEL];
    __shared__ int    selIdx[KSEL];
    __shared__ double cv[KSEL];
    __shared__ int    ci[KSEL];
    __shared__ float  fv[TOPK];
    __shared__ int    fi[TOPK];
    __shared__ int    scnt;

    int n = g_pcnt[row];
    if (n > POOLN) n = POOLN;

    for (int i = t; i < n; i += 256) {
        pv[i] = g_poolv[(size_t)row * POOLN + i];
        pc[i] = g_pooli[(size_t)row * POOLN + i];
    }
    for (int j = t; j < DMODEL; j += 256)
        xs[j] = X[(size_t)row * DMODEL + j];
    if (t == 0) scnt = 0;
    __syncthreads();

    // a) rank select: keep entries with rank < 32 (strict total order)
    for (int i = t; i < n; i += 256) {
        float vi = pv[i]; int cidx = pc[i];
        int rank = 0;
        for (int j = 0; j < n; ++j) {
            float vj = pv[j];
            rank += (vj > vi) || (vj == vi && pc[j] < cidx);
        }
        if (rank < KSEL) {
            int p = atomicAdd(&scnt, 1);
            selIdx[p] = cidx;
        }
    }
    __syncthreads();
    const int nsel = scnt;

    // b) fp64 refinement (8 warps, 4 candidates each)
    for (int c = w; c < nsel; c += 8) {
        int idx = selIdx[c];
        const float* wr = W + (size_t)idx * DMODEL;
        double acc = 0.0;
        #pragma unroll
        for (int j = 0; j < DMODEL / 32; ++j)
            acc += (double)xs[lane + j * 32] * (double)wr[lane + j * 32];
        #pragma unroll
        for (int off = 16; off > 0; off >>= 1)
            acc += __shfl_down_sync(0xffffffffu, acc, off);
        if (lane == 0) { cv[c] = acc + (double)benc[idx]; ci[c] = idx; }
    }
    __syncthreads();

    if (t == 0) {
        for (int kk = 0; kk < TOPK; ++kk) {
            double m = -1e300; int ms = 0;
            for (int k = 0; k < nsel; ++k)
                if (cv[k] > m) { m = cv[k]; ms = k; }
            fv[kk] = (float)m;
            fi[kk] = ci[ms];
            cv[ms] = -1e300;
        }
    }
    __syncthreads();

    // c) decode
    #pragma unroll
    for (int r = 0; r < 3; ++r) {
        int d = t + r * 256;
        float acc = bdec[d];
        #pragma unroll
        for (int k = 0; k < TOPK; ++k)
            acc += fv[k] * g_WdecT[(size_t)fi[k] * DMODEL + d];
        out[(size_t)row * DMODEL + d] = acc;
    }
}

// ============================================================
extern "C" void kernel_launch(void* const* d_in, const int* in_sizes, int n_in,
                              void* d_out, int out_size) {
    const float* x     = (const float*)d_in[0];
    const float* W_enc = (const float*)d_in[1];
    const float* b_enc = (const float*)d_in[2];
    const float* W_dec = (const float*)d_in[3];
    const float* b_dec = (const float*)d_in[4];
    float* out = (float*)d_out;

    float* sx; cudaGetSymbolAddress((void**)&sx, g_sx);
    float* sw; cudaGetSymbolAddress((void**)&sw, g_sw);
    int*   xq; cudaGetSymbolAddress((void**)&xq, g_Xq);
    int*   wq; cudaGetSymbolAddress((void**)&wq, g_Wq);

    zero_pcnt<<<(N_ROWS + 255) / 256, 256>>>();
    quant_kernel<<<N_ROWS,  192>>>(x,     xq, sx);
    quant_kernel<<<DLATENT, 192>>>(W_enc, wq, sw);
    transpose_wdec<<<dim3(DLATENT / 32, DMODEL / 32), dim3(32, 8)>>>(W_dec);
    encode_gemm_i8<<<dim3(DLATENT / IBN, N_ROWS / IBM), 256>>>(b_enc);
    tail_kernel<<<N_ROWS, 256>>>(x, W_enc, b_enc, b_dec, out);
}

// round 10
// speedup vs baseline: 1.0165x; 1.0165x over previous
#include <cuda_runtime.h>
#include <cstdint>

#define N_ROWS   16384
#define DMODEL   768
#define DLATENT  12288
#define TOPK     20
#define KSEL     32
#define POOLN    768                 // worst-row captures ~500; margin
#define KINT     (DMODEL / 4)        // 192 packed int32 per row
#define CAPTHR   2.0f

// ---- scratch (no allocation allowed -> __device__ globals) ----
__device__ float g_WdecT[(size_t)DLATENT * DMODEL];  // 37.7 MB
__device__ int   g_Xq [(size_t)N_ROWS * KINT];
__device__ int   g_Wq [(size_t)DLATENT * KINT];
__device__ int   g_XqT[(size_t)KINT * N_ROWS];       // [k][row]
__device__ int   g_WqT[(size_t)KINT * DLATENT];
__device__ float g_sx[N_ROWS];
__device__ float g_sw[DLATENT];
__device__ int   g_pcnt[N_ROWS];
__device__ float g_poolv[(size_t)N_ROWS * POOLN];
__device__ int   g_pooli[(size_t)N_ROWS * POOLN];

__global__ void zero_pcnt() {
    int i = blockIdx.x * 256 + threadIdx.x;
    if (i < N_ROWS) g_pcnt[i] = 0;
}

// ============================================================
// Kernel Q: per-row symmetric int8 quantization (coalesced)
// ============================================================
__global__ __launch_bounds__(192)
void quant_kernel(const float* __restrict__ src, int* __restrict__ dstq,
                  float* __restrict__ dscale) {
    const int row = blockIdx.x;
    const int t   = threadIdx.x;
    float4 v = *(const float4*)(src + (size_t)row * DMODEL + t * 4);
    float m = fmaxf(fmaxf(fabsf(v.x), fabsf(v.y)), fmaxf(fabsf(v.z), fabsf(v.w)));

    #pragma unroll
    for (int off = 16; off > 0; off >>= 1)
        m = fmaxf(m, __shfl_xor_sync(0xffffffffu, m, off));
    __shared__ float wm[6];
    __shared__ float smax;
    if ((t & 31) == 0) wm[t >> 5] = m;
    __syncthreads();
    if (t == 0) {
        float mm = wm[0];
        #pragma unroll
        for (int q = 1; q < 6; ++q) mm = fmaxf(mm, wm[q]);
        smax = mm;
        dscale[row] = mm / 127.0f;
    }
    __syncthreads();

    float inv = (smax > 0.f) ? 127.0f / smax : 0.f;
    int q0 = __float2int_rn(v.x * inv);
    int q1 = __float2int_rn(v.y * inv);
    int q2 = __float2int_rn(v.z * inv);
    int q3 = __float2int_rn(v.w * inv);
    dstq[(size_t)row * KINT + t] =
        (q0 & 0xFF) | ((q1 & 0xFF) << 8) | ((q2 & 0xFF) << 16) | (q3 << 24);
}

// ============================================================
// int tile transpose: src[rows][cols] -> dst[cols][rows]
// ============================================================
__global__ void transpose_int(const int* __restrict__ src, int* __restrict__ dst,
                              int rows, int cols) {
    __shared__ int tile[32][33];
    int c0 = blockIdx.x * 32;
    int r0 = blockIdx.y * 32;
    int tx = threadIdx.x, ty = threadIdx.y;   // (32,8)
    #pragma unroll
    for (int r = 0; r < 32; r += 8) {
        int rr = r0 + ty + r, cc = c0 + tx;
        if (rr < rows && cc < cols) tile[ty + r][tx] = src[(size_t)rr * cols + cc];
    }
    __syncthreads();
    #pragma unroll
    for (int r = 0; r < 32; r += 8) {
        int cc = c0 + ty + r, rr = r0 + tx;
        if (cc < cols && rr < rows) dst[(size_t)cc * rows + rr] = tile[tx][ty + r];
    }
}

// ============================================================
// Kernel 0: transpose W_dec [768,12288] -> W_decT [12288,768]
// ============================================================
__global__ void transpose_wdec(const float* __restrict__ Wdec) {
    __shared__ float tile[32][33];
    int l0 = blockIdx.x * 32;
    int d0 = blockIdx.y * 32;
    int tx = threadIdx.x, ty = threadIdx.y;
    #pragma unroll
    for (int r = 0; r < 32; r += 8)
        tile[ty + r][tx] = Wdec[(size_t)(d0 + ty + r) * DLATENT + l0 + tx];
    __syncthreads();
    #pragma unroll
    for (int r = 0; r < 32; r += 8)
        g_WdecT[(size_t)(l0 + ty + r) * DMODEL + d0 + tx] = tile[tx][ty + r];
}

// ============================================================
// Kernel 1: int8 dp4a encode GEMM — 3-stage cp.async pipeline,
// forced 2 CTAs/SM, fused threshold-capture epilogue.
// ============================================================
#define IBM 128
#define IBN 128
#define IBK 16
#define NKT (KINT / IBK)             // 12
#define NST 3

__device__ __forceinline__ void cp16(uint32_t dst, const void* src) {
    asm volatile("cp.async.cg.shared.global [%0], [%1], 16;" :: "r"(dst), "l"(src));
}

__global__ __launch_bounds__(256, 2)
void encode_gemm_i8(const float* __restrict__ benc) {
    __shared__ int As[NST][IBK][IBM];   // 8 KB per stage
    __shared__ int Bs[NST][IBK][IBN];

    const int t  = threadIdx.x;
    const int bn = blockIdx.x;
    const int bm = blockIdx.y;
    const int tm = t >> 4;
    const int tn = t & 15;

    const uint32_t sA = (uint32_t)__cvta_generic_to_shared(&As[0][0][0]);
    const uint32_t sB = (uint32_t)__cvta_generic_to_shared(&Bs[0][0][0]);

    // loader: thread owns chunks 2t, 2t+1 of 512 (16B each)
    const int kk0 = (2 * t) >> 5, m40 = (2 * t) & 31;
    const int kk1 = (2 * t + 1) >> 5, m41 = (2 * t + 1) & 31;

    int acc[8][8];
    #pragma unroll
    for (int i = 0; i < 8; ++i)
        #pragma unroll
        for (int j = 0; j < 8; ++j) acc[i][j] = 0;

    // prologue: stages 0,1
    #pragma unroll
    for (int s = 0; s < NST - 1; ++s) {
        const int kb = s * IBK;
        cp16(sA + ((s * IBK + kk0) * IBM + m40 * 4) * 4,
             g_XqT + (size_t)(kb + kk0) * N_ROWS + bm * IBM + m40 * 4);
        cp16(sA + ((s * IBK + kk1) * IBM + m41 * 4) * 4,
             g_XqT + (size_t)(kb + kk1) * N_ROWS + bm * IBM + m41 * 4);
        cp16(sB + ((s * IBK + kk0) * IBN + m40 * 4) * 4,
             g_WqT + (size_t)(kb + kk0) * DLATENT + bn * IBN + m40 * 4);
        cp16(sB + ((s * IBK + kk1) * IBN + m41 * 4) * 4,
             g_WqT + (size_t)(kb + kk1) * DLATENT + bn * IBN + m41 * 4);
        asm volatile("cp.async.commit_group;");
    }

    for (int kt = 0; kt < NKT; ++kt) {
        asm volatile("cp.async.wait_group 1;");
        __syncthreads();

        // issue stage kt+2 into slot (kt+2)%NST (freed: all warps finished kt-1)
        if (kt + 2 < NKT) {
            const int s  = (kt + 2) % NST;
            const int kb = (kt + 2) * IBK;
            cp16(sA + ((s * IBK + kk0) * IBM + m40 * 4) * 4,
                 g_XqT + (size_t)(kb + kk0) * N_ROWS + bm * IBM + m40 * 4);
            cp16(sA + ((s * IBK + kk1) * IBM + m41 * 4) * 4,
                 g_XqT + (size_t)(kb + kk1) * N_ROWS + bm * IBM + m41 * 4);
            cp16(sB + ((s * IBK + kk0) * IBN + m40 * 4) * 4,
                 g_WqT + (size_t)(kb + kk0) * DLATENT + bn * IBN + m40 * 4);
            cp16(sB + ((s * IBK + kk1) * IBN + m41 * 4) * 4,
                 g_WqT + (size_t)(kb + kk1) * DLATENT + bn * IBN + m41 * 4);
        }
        asm volatile("cp.async.commit_group;");

        const int buf = kt % NST;
        #pragma unroll
        for (int kk = 0; kk < IBK; ++kk) {
            int a[8], b[8];
            *(int4*)(a)     = *(const int4*)&As[buf][kk][tm * 8];
            *(int4*)(a + 4) = *(const int4*)&As[buf][kk][tm * 8 + 4];
            *(int4*)(b)     = *(const int4*)&Bs[buf][kk][tn * 8];
            *(int4*)(b + 4) = *(const int4*)&Bs[buf][kk][tn * 8 + 4];
            #pragma unroll
            for (int i = 0; i < 8; ++i)
                #pragma unroll
                for (int j = 0; j < 8; ++j)
                    acc[i][j] = __dp4a(a[i], b[j], acc[i][j]);
        }
    }

    // epilogue: per-row capture (few live values at a time)
    const int gcol = bn * IBN + tn * 8;
    float sw_[8], bias[8];
    #pragma unroll
    for (int j = 0; j < 8; ++j) {
        sw_[j]  = g_sw[gcol + j];
        bias[j] = __ldg(&benc[gcol + j]);
    }
    #pragma unroll
    for (int i = 0; i < 8; ++i) {
        const int grow = bm * IBM + tm * 8 + i;
        const float s = g_sx[grow];
        #pragma unroll
        for (int j = 0; j < 8; ++j) {
            float v = (float)acc[i][j] * s * sw_[j] + bias[j];
            if (v > CAPTHR) {
                int p = atomicAdd(&g_pcnt[grow], 1);
                if (p < POOLN) {
                    g_poolv[(size_t)grow * POOLN + p] = v;
                    g_pooli[(size_t)grow * POOLN + p] = gcol + j;
                }
            }
        }
    }
}

// ============================================================
// Kernel 2 (fused tail): rank-select top-32 -> fp64 refine -> decode
// ============================================================
__global__ __launch_bounds__(256)
void tail_kernel(const float* __restrict__ X,
                 const float* __restrict__ W,
                 const float* __restrict__ benc,
                 const float* __restrict__ bdec,
                 float* __restrict__ out) {
    const int row  = blockIdx.x;
    const int t    = threadIdx.x;
    const int w    = t >> 5;
    const int lane = t & 31;

    __shared__ float  pv[POOLN];
    __shared__ int    pc[POOLN];
    __shared__ float  xs[DMODEL];
    __shared__ int    selIdx[KSEL];
    __shared__ double cv[KSEL];
    __shared__ int    ci[KSEL];
    __shared__ float  fv[TOPK];
    __shared__ int    fi[TOPK];
    __shared__ int    scnt;

    int n = g_pcnt[row];
    if (n > POOLN) n = POOLN;

    for (int i = t; i < n; i += 256) {
        pv[i] = g_poolv[(size_t)row * POOLN + i];
        pc[i] = g_pooli[(size_t)row * POOLN + i];
    }
    for (int j = t; j < DMODEL; j += 256)
        xs[j] = X[(size_t)row * DMODEL + j];
    if (t == 0) scnt = 0;
    __syncthreads();

    // a) rank-select top-KSEL (strict total order)
    for (int i = t; i < n; i += 256) {
        float vi = pv[i]; int cidx = pc[i];
        int rank = 0;
        for (int j = 0; j < n; ++j) {
            float vj = pv[j];
            rank += (vj > vi) || (vj == vi && pc[j] < cidx);
        }
        if (rank < KSEL) {
            int p = atomicAdd(&scnt, 1);
            selIdx[p] = cidx;
        }
    }
    __syncthreads();
    const int nsel = scnt;

    // b) fp64 refinement
    for (int c = w; c < nsel; c += 8) {
        int idx = selIdx[c];
        const float* wr = W + (size_t)idx * DMODEL;
        double acc = 0.0;
        #pragma unroll
        for (int j = 0; j < DMODEL / 32; ++j)
            acc += (double)xs[lane + j * 32] * (double)wr[lane + j * 32];
        #pragma unroll
        for (int off = 16; off > 0; off >>= 1)
            acc += __shfl_down_sync(0xffffffffu, acc, off);
        if (lane == 0) { cv[c] = acc + (double)benc[idx]; ci[c] = idx; }
    }
    __syncthreads();

    if (t == 0) {
        for (int kk = 0; kk < TOPK; ++kk) {
            double m = -1e300; int ms = 0;
            for (int k = 0; k < nsel; ++k)
                if (cv[k] > m) { m = cv[k]; ms = k; }
            fv[kk] = (float)m;
            fi[kk] = ci[ms];
            cv[ms] = -1e300;
        }
    }
    __syncthreads();

    // c) decode
    #pragma unroll
    for (int r = 0; r < 3; ++r) {
        int d = t + r * 256;
        float acc = bdec[d];
        #pragma unroll
        for (int k = 0; k < TOPK; ++k)
            acc += fv[k] * g_WdecT[(size_t)fi[k] * DMODEL + d];
        out[(size_t)row * DMODEL + d] = acc;
    }
}

// ============================================================
extern "C" void kernel_launch(void* const* d_in, const int* in_sizes, int n_in,
                              void* d_out, int out_size) {
    const float* x     = (const float*)d_in[0];
    const float* W_enc = (const float*)d_in[1];
    const float* b_enc = (const float*)d_in[2];
    const float* W_dec = (const float*)d_in[3];
    const float* b_dec = (const float*)d_in[4];
    float* out = (float*)d_out;

    float* sx;  cudaGetSymbolAddress((void**)&sx,  g_sx);
    float* sw;  cudaGetSymbolAddress((void**)&sw,  g_sw);
    int*   xq;  cudaGetSymbolAddress((void**)&xq,  g_Xq);
    int*   wq;  cudaGetSymbolAddress((void**)&wq,  g_Wq);
    int*   xqt; cudaGetSymbolAddress((void**)&xqt, g_XqT);
    int*   wqt; cudaGetSymbolAddress((void**)&wqt, g_WqT);

    zero_pcnt<<<(N_ROWS + 255) / 256, 256>>>();
    quant_kernel<<<N_ROWS,  192>>>(x,     xq, sx);
    quant_kernel<<<DLATENT, 192>>>(W_enc, wq, sw);
    transpose_int<<<dim3(KINT / 32 + 1, N_ROWS / 32), dim3(32, 8)>>>(xq, xqt, N_ROWS, KINT);
    transpose_int<<<dim3(KINT / 32 + 1, DLATENT / 32), dim3(32, 8)>>>(wq, wqt, DLATENT, KINT);
    transpose_wdec<<<dim3(DLATENT / 32, DMODEL / 32), dim3(32, 8)>>>(W_dec);
    encode_gemm_i8<<<dim3(DLATENT / IBN, N_ROWS / IBM), 256>>>(b_enc);
    tail_kernel<<<N_ROWS, 256>>>(x, W_enc, b_enc, b_dec, out);
}

// round 11
// speedup vs baseline: 1.5977x; 1.5717x over previous
#include <cuda_runtime.h>
#include <cstdint>

#define N_ROWS   16384
#define DMODEL   768
#define DLATENT  12288
#define TOPK     20
#define NCMAX    128                 // max candidates per row

// ---- scratch (no allocation allowed -> __device__ globals) ----
__device__ float g_lat[(size_t)N_ROWS * DLATENT];    // 805 MB latents
__device__ int   g_cidx[(size_t)N_ROWS * NCMAX];
__device__ int   g_ccnt[N_ROWS];
__device__ float g_vals[N_ROWS * TOPK];
__device__ int   g_idx [N_ROWS * TOPK];
__device__ float g_WdecT[(size_t)DLATENT * DMODEL];  // 37.7 MB

// ============================================================
// Kernel 0: transpose W_dec [768,12288] -> W_decT [12288,768]
// ============================================================
__global__ void transpose_wdec(const float* __restrict__ Wdec) {
    __shared__ float tile[32][33];
    int l0 = blockIdx.x * 32;
    int d0 = blockIdx.y * 32;
    int tx = threadIdx.x, ty = threadIdx.y;   // (32,8)
    #pragma unroll
    for (int r = 0; r < 32; r += 8)
        tile[ty + r][tx] = Wdec[(size_t)(d0 + ty + r) * DLATENT + l0 + tx];
    __syncthreads();
    #pragma unroll
    for (int r = 0; r < 32; r += 8)
        g_WdecT[(size_t)(l0 + ty + r) * DMODEL + d0 + tx] = tile[tx][ty + r];
}

// ============================================================
// Kernel 1: encode GEMM  latents = X * W_enc^T + b_enc (tf32 mma.sync)
//   CTA 128x128x32, 3-stage cp.async pipeline, ldmatrix fragments.
//   (R3 kernel verbatim — measured ~1.85 ms)
// ============================================================
#define BM 128
#define BN 128
#define BK 32
#define BKP 36                      // padded row stride (floats)
#define STAGE_FLOATS (2 * BM * BKP)
#define STAGE_BYTES  (STAGE_FLOATS * 4)
#define NSTAGE 3
#define GEMM_SMEM (NSTAGE * STAGE_BYTES)   // 110592 bytes

__device__ __forceinline__ void cp16(uint32_t dst, const float* src) {
    asm volatile("cp.async.cg.shared.global [%0], [%1], 16;" :: "r"(dst), "l"(src));
}
__device__ __forceinline__ void ldsm4(uint32_t& r0, uint32_t& r1,
                                      uint32_t& r2, uint32_t& r3, uint32_t addr) {
    asm volatile("ldmatrix.sync.aligned.m8n8.x4.shared.b16 {%0,%1,%2,%3}, [%4];"
                 : "=r"(r0), "=r"(r1), "=r"(r2), "=r"(r3) : "r"(addr));
}

extern __shared__ float dynsmem[];

__global__ __launch_bounds__(256)
void encode_gemm(const float* __restrict__ X,
                 const float* __restrict__ W,
                 const float* __restrict__ benc) {
    const int t    = threadIdx.x;
    const int bm   = blockIdx.y;
    const int bn   = blockIdx.x;
    const int w    = t >> 5;
    const int lane = t & 31;
    const int wm   = (w >> 2) * 64;
    const int wn   = (w & 3) * 32;
    const int grp  = lane >> 2;
    const int qid  = lane & 3;

    const uint32_t smem_base = (uint32_t)__cvta_generic_to_shared(dynsmem);

    const int lrow = t >> 3;          // 0..31
    const int lk   = (t & 7) * 4;     // 0,4,...,28
    const float* Ag = X + (size_t)(bm * BM + lrow) * DMODEL + lk;
    const float* Bg = W + (size_t)(bn * BN + lrow) * DMODEL + lk;
    const uint32_t sA = smem_base + (lrow * BKP + lk) * 4;
    const uint32_t sB = sA + BM * BKP * 4;

    const int arow = lane & 15;
    const int acol = (lane & 16) ? 4 : 0;
    const int brow = (lane & 7) + ((lane & 16) >> 1);
    const int bcol = (lane & 8) ? 4 : 0;
    const uint32_t aBase = smem_base + ((wm + arow) * BKP + acol) * 4;
    const uint32_t bBase = smem_base + BM * BKP * 4 + ((wn + brow) * BKP + bcol) * 4;

    float c[4][4][4];
    #pragma unroll
    for (int i = 0; i < 4; ++i)
        #pragma unroll
        for (int j = 0; j < 4; ++j)
            #pragma unroll
            for (int q = 0; q < 4; ++q) c[i][j][q] = 0.f;

    const int KT = DMODEL / BK;       // 24

    #pragma unroll
    for (int s = 0; s < NSTAGE - 1; ++s) {
        #pragma unroll
        for (int r = 0; r < 4; ++r) {
            cp16(sA + s * STAGE_BYTES + r * 32 * BKP * 4, Ag + s * BK + (size_t)r * 32 * DMODEL);
            cp16(sB + s * STAGE_BYTES + r * 32 * BKP * 4, Bg + s * BK + (size_t)r * 32 * DMODEL);
        }
        asm volatile("cp.async.commit_group;");
    }

    for (int kt = 0; kt < KT; ++kt) {
        asm volatile("cp.async.wait_group %0;" :: "n"(NSTAGE - 2));
        __syncthreads();

        {
            int nxt = kt + NSTAGE - 1;
            if (nxt < KT) {
                int s = nxt % NSTAGE;
                #pragma unroll
                for (int r = 0; r < 4; ++r) {
                    cp16(sA + s * STAGE_BYTES + r * 32 * BKP * 4, Ag + nxt * BK + (size_t)r * 32 * DMODEL);
                    cp16(sB + s * STAGE_BYTES + r * 32 * BKP * 4, Bg + nxt * BK + (size_t)r * 32 * DMODEL);
                }
            }
            asm volatile("cp.async.commit_group;");
        }

        const uint32_t stoff = (uint32_t)(kt % NSTAGE) * STAGE_BYTES;

        #pragma unroll
        for (int ks = 0; ks < 4; ++ks) {
            const int k8 = ks * 8;
            uint32_t a[4][4], bf[4][2];
            #pragma unroll
            for (int i = 0; i < 4; ++i)
                ldsm4(a[i][0], a[i][1], a[i][2], a[i][3],
                      aBase + stoff + (i * 16 * BKP + k8) * 4);
            #pragma unroll
            for (int jp = 0; jp < 2; ++jp)
                ldsm4(bf[2 * jp][0], bf[2 * jp][1], bf[2 * jp + 1][0], bf[2 * jp + 1][1],
                      bBase + stoff + (jp * 16 * BKP + k8) * 4);
            #pragma unroll
            for (int i = 0; i < 4; ++i)
                #pragma unroll
                for (int j = 0; j < 4; ++j) {
                    asm volatile(
                        "mma.sync.aligned.m16n8k8.row.col.f32.tf32.tf32.f32 "
                        "{%0,%1,%2,%3}, {%4,%5,%6,%7}, {%8,%9}, {%0,%1,%2,%3};"
                        : "+f"(c[i][j][0]), "+f"(c[i][j][1]),
                          "+f"(c[i][j][2]), "+f"(c[i][j][3])
                        : "r"(a[i][0]), "r"(a[i][1]), "r"(a[i][2]), "r"(a[i][3]),
                          "r"(bf[j][0]), "r"(bf[j][1]));
                }
        }
    }

    #pragma unroll
    for (int j = 0; j < 4; ++j) {
        int cg = bn * BN + wn + j * 8 + 2 * qid;
        float b0 = benc[cg], b1 = benc[cg + 1];
        #pragma unroll
        for (int i = 0; i < 4; ++i) {
            int rg = bm * BM + wm + i * 16 + grp;
            float2 v0 = make_float2(c[i][j][0] + b0, c[i][j][1] + b1);
            float2 v1 = make_float2(c[i][j][2] + b0, c[i][j][3] + b1);
            *(float2*)&g_lat[(size_t)rg * DLATENT + cg]       = v0;
            *(float2*)&g_lat[(size_t)(rg + 8) * DLATENT + cg] = v1;
        }
    }
}

// ============================================================
// Kernel 2: histogram-threshold candidate select (R7 verbatim).
// ============================================================
__device__ __forceinline__ uint32_t mono_key(float v) {
    uint32_t u = __float_as_uint(v);
    return ((int)u < 0) ? ~u : (u | 0x80000000u);
}

__global__ __launch_bounds__(256)
void topk_cand_kernel() {
    const int row = blockIdx.x;
    const int t   = threadIdx.x;   // 256
    const float* lat = g_lat + (size_t)row * DLATENT;

    __shared__ uint32_t hist[4096];
    __shared__ uint32_t S[256];
    __shared__ uint32_t thrKey;
    __shared__ int      segIdx;
    __shared__ int      cnt;

    #pragma unroll
    for (int i = 0; i < 16; ++i) hist[t + i * 256] = 0;
    if (t == 0) { cnt = 0; segIdx = -1; }
    __syncthreads();

    #pragma unroll
    for (int i = 0; i < 12; ++i) {
        float4 v = *(const float4*)(lat + (t + i * 256) * 4);
        atomicAdd(&hist[mono_key(v.x) >> 20], 1u);
        atomicAdd(&hist[mono_key(v.y) >> 20], 1u);
        atomicAdd(&hist[mono_key(v.z) >> 20], 1u);
        atomicAdd(&hist[mono_key(v.w) >> 20], 1u);
    }
    __syncthreads();

    uint32_t s = 0;
    #pragma unroll
    for (int i = 0; i < 16; ++i) s += hist[t * 16 + i];
    S[t] = s;
    __syncthreads();
    #pragma unroll
    for (int off = 1; off < 256; off <<= 1) {
        uint32_t v = (t + off < 256) ? S[t + off] : 0;
        __syncthreads();
        S[t] += v;
        __syncthreads();
    }
    uint32_t snext = (t < 255) ? S[t + 1] : 0;
    if (S[t] >= 32 && snext < 32) segIdx = t;
    __syncthreads();

    if (t == 0) {
        int seg = segIdx;
        uint32_t cum = (seg < 255) ? S[seg + 1] : 0;
        int b = seg * 16 + 15;
        while (b >= seg * 16) {
            cum += hist[b];
            if (cum >= 32) break;
            --b;
        }
        thrKey = (uint32_t)b << 20;
    }
    __syncthreads();

    const uint32_t th = thrKey;
    #pragma unroll
    for (int i = 0; i < 12; ++i) {
        int col = (t + i * 256) * 4;
        float4 v = *(const float4*)(lat + col);
        uint32_t k0 = mono_key(v.x), k1 = mono_key(v.y);
        uint32_t k2 = mono_key(v.z), k3 = mono_key(v.w);
        if (k0 >= th) { int p = atomicAdd(&cnt, 1); if (p < NCMAX) g_cidx[(size_t)row * NCMAX + p] = col; }
        if (k1 >= th) { int p = atomicAdd(&cnt, 1); if (p < NCMAX) g_cidx[(size_t)row * NCMAX + p] = col + 1; }
        if (k2 >= th) { int p = atomicAdd(&cnt, 1); if (p < NCMAX) g_cidx[(size_t)row * NCMAX + p] = col + 2; }
        if (k3 >= th) { int p = atomicAdd(&cnt, 1); if (p < NCMAX) g_cidx[(size_t)row * NCMAX + p] = col + 3; }
    }
    __syncthreads();
    if (t == 0) g_ccnt[row] = (cnt < NCMAX) ? cnt : NCMAX;
}

// ============================================================
// Kernel 3: fp64 refinement — exact top-20 from <=128 candidates
// ============================================================
__global__ __launch_bounds__(256)
void refine_kernel(const float* __restrict__ X,
                   const float* __restrict__ W,
                   const float* __restrict__ benc) {
    const int row  = blockIdx.x;
    const int t    = threadIdx.x;
    const int w    = t >> 5;
    const int lane = t & 31;
    const int n    = g_ccnt[row];

    __shared__ float  xs[DMODEL];
    __shared__ double cv[NCMAX];
    __shared__ int    ci[NCMAX];

    for (int j = t; j < DMODEL; j += 256)
        xs[j] = X[(size_t)row * DMODEL + j];
    for (int c = t; c < NCMAX; c += 256) cv[c] = -1e300;
    __syncthreads();

    for (int c = w; c < n; c += 8) {
        int idx = g_cidx[(size_t)row * NCMAX + c];
        const float* wr = W + (size_t)idx * DMODEL;
        double acc = 0.0;
        #pragma unroll
        for (int j = 0; j < DMODEL / 32; ++j)
            acc += (double)xs[lane + j * 32] * (double)wr[lane + j * 32];
        #pragma unroll
        for (int off = 16; off > 0; off >>= 1)
            acc += __shfl_down_sync(0xffffffffu, acc, off);
        if (lane == 0) { cv[c] = acc + (double)benc[idx]; ci[c] = idx; }
    }
    __syncthreads();

    if (t == 0) {
        for (int kk = 0; kk < TOPK; ++kk) {
            double m = -1e300; int ms = 0;
            for (int k = 0; k < n; ++k)
                if (cv[k] > m) { m = cv[k]; ms = k; }
            g_vals[row * TOPK + kk] = (float)m;
            g_idx [row * TOPK + kk] = ci[ms];
            cv[ms] = -1e300;
        }
    }
}

// ============================================================
// Kernel 4: decode
// ============================================================
__global__ __launch_bounds__(256)
void decode_kernel(const float* __restrict__ bdec,
                   float* __restrict__ out) {
    const int row = blockIdx.x;
    const int t   = threadIdx.x;
    __shared__ float v[TOPK];
    __shared__ int   id[TOPK];
    if (t < TOPK) { v[t] = g_vals[row * TOPK + t]; id[t] = g_idx[row * TOPK + t]; }
    __syncthreads();

    #pragma unroll
    for (int r = 0; r < 3; ++r) {
        int d = t + r * 256;
        float acc = bdec[d];
        #pragma unroll
        for (int k = 0; k < TOPK; ++k)
            acc += v[k] * g_WdecT[(size_t)id[k] * DMODEL + d];
        out[(size_t)row * DMODEL + d] = acc;
    }
}

// ============================================================
extern "C" void kernel_launch(void* const* d_in, const int* in_sizes, int n_in,
                              void* d_out, int out_size) {
    const float* x     = (const float*)d_in[0];
    const float* W_enc = (const float*)d_in[1];
    const float* b_enc = (const float*)d_in[2];
    const float* W_dec = (const float*)d_in[3];
    const float* b_dec = (const float*)d_in[4];
    float* out = (float*)d_out;

    cudaFuncSetAttribute(encode_gemm, cudaFuncAttributeMaxDynamicSharedMemorySize, GEMM_SMEM);

    transpose_wdec<<<dim3(DLATENT / 32, DMODEL / 32), dim3(32, 8)>>>(W_dec);
    encode_gemm<<<dim3(DLATENT / BN, N_ROWS / BM), 256, GEMM_SMEM>>>(x, W_enc, b_enc);
    topk_cand_kernel<<<N_ROWS, 256>>>();
    refine_kernel<<<N_ROWS, 256>>>(x, W_enc, b_enc);
    decode_kernel<<<N_ROWS, 256>>>(b_dec, out);
}

// round 12
// speedup vs baseline: 2.2169x; 1.3875x over previous
#include <cuda_runtime.h>
#include <cuda_bf16.h>
#include <cstdint>

#define N_ROWS   16384
#define DMODEL   768
#define DLATENT  12288
#define TOPK     20
#define NCMAX    128

// ---- scratch (no allocation allowed -> __device__ globals) ----
__device__ float g_lat[(size_t)N_ROWS * DLATENT];    // 805 MB latents
__device__ int   g_cidx[(size_t)N_ROWS * NCMAX];
__device__ int   g_ccnt[N_ROWS];
__device__ float g_vals[N_ROWS * TOPK];
__device__ int   g_idx [N_ROWS * TOPK];
__device__ float g_WdecT[(size_t)DLATENT * DMODEL];  // 37.7 MB
__device__ __nv_bfloat16 g_Xbf[(size_t)N_ROWS * DMODEL];   // 25 MB
__device__ __nv_bfloat16 g_Wbf[(size_t)DLATENT * DMODEL];  // 19 MB

// ============================================================
// Kernel A: fp32 -> bf16 conversion (row-major, coalesced)
// ============================================================
__global__ void convert_bf16(const float* __restrict__ X, const float* __restrict__ W) {
    const size_t nx = (size_t)N_ROWS * DMODEL / 2;
    const size_t nw = (size_t)DLATENT * DMODEL / 2;
    size_t i = (size_t)blockIdx.x * blockDim.x + threadIdx.x;
    if (i < nx) {
        float2 v = ((const float2*)X)[i];
        ((__nv_bfloat162*)g_Xbf)[i] = __floats2bfloat162_rn(v.x, v.y);
    } else if (i < nx + nw) {
        float2 v = ((const float2*)W)[i - nx];
        ((__nv_bfloat162*)g_Wbf)[i - nx] = __floats2bfloat162_rn(v.x, v.y);
    }
}

// ============================================================
// Kernel 0: transpose W_dec [768,12288] -> W_decT [12288,768]
// ============================================================
__global__ void transpose_wdec(const float* __restrict__ Wdec) {
    __shared__ float tile[32][33];
    int l0 = blockIdx.x * 32;
    int d0 = blockIdx.y * 32;
    int tx = threadIdx.x, ty = threadIdx.y;
    #pragma unroll
    for (int r = 0; r < 32; r += 8)
        tile[ty + r][tx] = Wdec[(size_t)(d0 + ty + r) * DLATENT + l0 + tx];
    __syncthreads();
    #pragma unroll
    for (int r = 0; r < 32; r += 8)
        g_WdecT[(size_t)(l0 + ty + r) * DMODEL + d0 + tx] = tile[tx][ty + r];
}

// ============================================================
// Kernel 1: encode GEMM  latents = X * W_enc^T + b_enc
//   bf16 mma.sync m16n8k16, CTA 128x128x32(bf16), 3-stage cp.async.
//   smem row stride 80 B -> ldmatrix conflict-free.
// ============================================================
#define BM 128
#define BN 128
#define BK 32                        // bf16 elements per k-tile
#define ROWB 80                      // padded row stride in bytes (40 halves)
#define STAGE_BYTES (2 * BM * ROWB)  // A + B per stage = 20480
#define NSTAGE 3
#define GEMM_SMEM (NSTAGE * STAGE_BYTES)   // 61440 bytes

__device__ __forceinline__ void cp16(uint32_t dst, const void* src) {
    asm volatile("cp.async.cg.shared.global [%0], [%1], 16;" :: "r"(dst), "l"(src));
}
__device__ __forceinline__ void ldsm4(uint32_t& r0, uint32_t& r1,
                                      uint32_t& r2, uint32_t& r3, uint32_t addr) {
    asm volatile("ldmatrix.sync.aligned.m8n8.x4.shared.b16 {%0,%1,%2,%3}, [%4];"
                 : "=r"(r0), "=r"(r1), "=r"(r2), "=r"(r3) : "r"(addr));
}

extern __shared__ char dynsmem[];

__global__ __launch_bounds__(256)
void encode_gemm(const float* __restrict__ benc) {
    const int t    = threadIdx.x;
    const int bm   = blockIdx.y;
    const int bn   = blockIdx.x;
    const int w    = t >> 5;
    const int lane = t & 31;
    const int wm   = (w >> 2) * 64;
    const int wn   = (w & 3) * 32;
    const int grp  = lane >> 2;
    const int qid  = lane & 3;

    const uint32_t smem_base = (uint32_t)__cvta_generic_to_shared(dynsmem);

    // loader: 512 chunks (16B) per matrix per stage; thread t owns chunks t, t+256
    const int lr0 = t >> 2;          // 0..63
    const int lch = t & 3;           // chunk within row (16B each, 4 per 64B row)
    const __nv_bfloat16* Ag = g_Xbf + (size_t)(bm * BM) * DMODEL;
    const __nv_bfloat16* Bg = g_Wbf + (size_t)(bn * BN) * DMODEL;

    // ldmatrix per-lane addresses
    const int arow = lane & 15;
    const int abyt = (lane & 16) ? 16 : 0;
    const int brow = (lane & 7) + ((lane & 16) >> 1);
    const int bbyt = (lane & 8) ? 16 : 0;
    const uint32_t aBase = smem_base + (wm + arow) * ROWB + abyt;
    const uint32_t bBase = smem_base + BM * ROWB + (wn + brow) * ROWB + bbyt;

    float c[4][4][4];
    #pragma unroll
    for (int i = 0; i < 4; ++i)
        #pragma unroll
        for (int j = 0; j < 4; ++j)
            #pragma unroll
            for (int q = 0; q < 4; ++q) c[i][j][q] = 0.f;

    const int KT = DMODEL / BK;       // 24

    #pragma unroll
    for (int s = 0; s < NSTAGE - 1; ++s) {
        const uint32_t so = s * STAGE_BYTES;
        cp16(smem_base + so + lr0 * ROWB + lch * 16,
             Ag + (size_t)lr0 * DMODEL + s * BK + lch * 8);
        cp16(smem_base + so + (lr0 + 64) * ROWB + lch * 16,
             Ag + (size_t)(lr0 + 64) * DMODEL + s * BK + lch * 8);
        cp16(smem_base + so + BM * ROWB + lr0 * ROWB + lch * 16,
             Bg + (size_t)lr0 * DMODEL + s * BK + lch * 8);
        cp16(smem_base + so + BM * ROWB + (lr0 + 64) * ROWB + lch * 16,
             Bg + (size_t)(lr0 + 64) * DMODEL + s * BK + lch * 8);
        asm volatile("cp.async.commit_group;");
    }

    for (int kt = 0; kt < KT; ++kt) {
        asm volatile("cp.async.wait_group %0;" :: "n"(NSTAGE - 2));
        __syncthreads();

        {
            int nxt = kt + NSTAGE - 1;
            if (nxt < KT) {
                const uint32_t so = (nxt % NSTAGE) * STAGE_BYTES;
                cp16(smem_base + so + lr0 * ROWB + lch * 16,
                     Ag + (size_t)lr0 * DMODEL + nxt * BK + lch * 8);
                cp16(smem_base + so + (lr0 + 64) * ROWB + lch * 16,
                     Ag + (size_t)(lr0 + 64) * DMODEL + nxt * BK + lch * 8);
                cp16(smem_base + so + BM * ROWB + lr0 * ROWB + lch * 16,
                     Bg + (size_t)lr0 * DMODEL + nxt * BK + lch * 8);
                cp16(smem_base + so + BM * ROWB + (lr0 + 64) * ROWB + lch * 16,
                     Bg + (size_t)(lr0 + 64) * DMODEL + nxt * BK + lch * 8);
            }
            asm volatile("cp.async.commit_group;");
        }

        const uint32_t stoff = (uint32_t)(kt % NSTAGE) * STAGE_BYTES;

        #pragma unroll
        for (int ks = 0; ks < 2; ++ks) {      // two k16 steps per 32-wide tile
            const uint32_t ko = ks * 32;      // 16 bf16 = 32 bytes
            uint32_t a[4][4], bf[4][2];
            #pragma unroll
            for (int i = 0; i < 4; ++i)
                ldsm4(a[i][0], a[i][1], a[i][2], a[i][3],
                      aBase + stoff + i * 16 * ROWB + ko);
            #pragma unroll
            for (int jp = 0; jp < 2; ++jp)
                ldsm4(bf[2 * jp][0], bf[2 * jp][1], bf[2 * jp + 1][0], bf[2 * jp + 1][1],
                      bBase + stoff + jp * 16 * ROWB + ko);
            #pragma unroll
            for (int i = 0; i < 4; ++i)
                #pragma unroll
                for (int j = 0; j < 4; ++j) {
                    asm volatile(
                        "mma.sync.aligned.m16n8k16.row.col.f32.bf16.bf16.f32 "
                        "{%0,%1,%2,%3}, {%4,%5,%6,%7}, {%8,%9}, {%0,%1,%2,%3};"
                        : "+f"(c[i][j][0]), "+f"(c[i][j][1]),
                          "+f"(c[i][j][2]), "+f"(c[i][j][3])
                        : "r"(a[i][0]), "r"(a[i][1]), "r"(a[i][2]), "r"(a[i][3]),
                          "r"(bf[j][0]), "r"(bf[j][1]));
                }
        }
    }

    // epilogue: + b_enc, store latents (accumulator layout same as k8)
    #pragma unroll
    for (int j = 0; j < 4; ++j) {
        int cg = bn * BN + wn + j * 8 + 2 * qid;
        float b0 = benc[cg], b1 = benc[cg + 1];
        #pragma unroll
        for (int i = 0; i < 4; ++i) {
            int rg = bm * BM + wm + i * 16 + grp;
            float2 v0 = make_float2(c[i][j][0] + b0, c[i][j][1] + b1);
            float2 v1 = make_float2(c[i][j][2] + b0, c[i][j][3] + b1);
            *(float2*)&g_lat[(size_t)rg * DLATENT + cg]       = v0;
            *(float2*)&g_lat[(size_t)(rg + 8) * DLATENT + cg] = v1;
        }
    }
}

// ============================================================
// Kernel 2: histogram-threshold candidate select (R7/R11 verbatim)
// ============================================================
__device__ __forceinline__ uint32_t mono_key(float v) {
    uint32_t u = __float_as_uint(v);
    return ((int)u < 0) ? ~u : (u | 0x80000000u);
}

__global__ __launch_bounds__(256)
void topk_cand_kernel() {
    const int row = blockIdx.x;
    const int t   = threadIdx.x;
    const float* lat = g_lat + (size_t)row * DLATENT;

    __shared__ uint32_t hist[4096];
    __shared__ uint32_t S[256];
    __shared__ uint32_t thrKey;
    __shared__ int      segIdx;
    __shared__ int      cnt;

    #pragma unroll
    for (int i = 0; i < 16; ++i) hist[t + i * 256] = 0;
    if (t == 0) { cnt = 0; segIdx = -1; }
    __syncthreads();

    #pragma unroll
    for (int i = 0; i < 12; ++i) {
        float4 v = *(const float4*)(lat + (t + i * 256) * 4);
        atomicAdd(&hist[mono_key(v.x) >> 20], 1u);
        atomicAdd(&hist[mono_key(v.y) >> 20], 1u);
        atomicAdd(&hist[mono_key(v.z) >> 20], 1u);
        atomicAdd(&hist[mono_key(v.w) >> 20], 1u);
    }
    __syncthreads();

    uint32_t s = 0;
    #pragma unroll
    for (int i = 0; i < 16; ++i) s += hist[t * 16 + i];
    S[t] = s;
    __syncthreads();
    #pragma unroll
    for (int off = 1; off < 256; off <<= 1) {
        uint32_t v = (t + off < 256) ? S[t + off] : 0;
        __syncthreads();
        S[t] += v;
        __syncthreads();
    }
    uint32_t snext = (t < 255) ? S[t + 1] : 0;
    if (S[t] >= 32 && snext < 32) segIdx = t;
    __syncthreads();

    if (t == 0) {
        int seg = segIdx;
        uint32_t cum = (seg < 255) ? S[seg + 1] : 0;
        int b = seg * 16 + 15;
        while (b >= seg * 16) {
            cum += hist[b];
            if (cum >= 32) break;
            --b;
        }
        thrKey = (uint32_t)b << 20;
    }
    __syncthreads();

    const uint32_t th = thrKey;
    #pragma unroll
    for (int i = 0; i < 12; ++i) {
        int col = (t + i * 256) * 4;
        float4 v = *(const float4*)(lat + col);
        uint32_t k0 = mono_key(v.x), k1 = mono_key(v.y);
        uint32_t k2 = mono_key(v.z), k3 = mono_key(v.w);
        if (k0 >= th) { int p = atomicAdd(&cnt, 1); if (p < NCMAX) g_cidx[(size_t)row * NCMAX + p] = col; }
        if (k1 >= th) { int p = atomicAdd(&cnt, 1); if (p < NCMAX) g_cidx[(size_t)row * NCMAX + p] = col + 1; }
        if (k2 >= th) { int p = atomicAdd(&cnt, 1); if (p < NCMAX) g_cidx[(size_t)row * NCMAX + p] = col + 2; }
        if (k3 >= th) { int p = atomicAdd(&cnt, 1); if (p < NCMAX) g_cidx[(size_t)row * NCMAX + p] = col + 3; }
    }
    __syncthreads();
    if (t == 0) g_ccnt[row] = (cnt < NCMAX) ? cnt : NCMAX;
}

// ============================================================
// Kernel 3: fp64 refinement — exact top-20 from <=128 candidates
// ============================================================
__global__ __launch_bounds__(256)
void refine_kernel(const float* __restrict__ X,
                   const float* __restrict__ W,
                   const float* __restrict__ benc) {
    const int row  = blockIdx.x;
    const int t    = threadIdx.x;
    const int w    = t >> 5;
    const int lane = t & 31;
    const int n    = g_ccnt[row];

    __shared__ float  xs[DMODEL];
    __shared__ double cv[NCMAX];
    __shared__ int    ci[NCMAX];

    for (int j = t; j < DMODEL; j += 256)
        xs[j] = X[(size_t)row * DMODEL + j];
    for (int c = t; c < NCMAX; c += 256) cv[c] = -1e300;
    __syncthreads();

    for (int c = w; c < n; c += 8) {
        int idx = g_cidx[(size_t)row * NCMAX + c];
        const float* wr = W + (size_t)idx * DMODEL;
        double acc = 0.0;
        #pragma unroll
        for (int j = 0; j < DMODEL / 32; ++j)
            acc += (double)xs[lane + j * 32] * (double)wr[lane + j * 32];
        #pragma unroll
        for (int off = 16; off > 0; off >>= 1)
            acc += __shfl_down_sync(0xffffffffu, acc, off);
        if (lane == 0) { cv[c] = acc + (double)benc[idx]; ci[c] = idx; }
    }
    __syncthreads();

    if (t == 0) {
        for (int kk = 0; kk < TOPK; ++kk) {
            double m = -1e300; int ms = 0;
            for (int k = 0; k < n; ++k)
                if (cv[k] > m) { m = cv[k]; ms = k; }
            g_vals[row * TOPK + kk] = (float)m;
            g_idx [row * TOPK + kk] = ci[ms];
            cv[ms] = -1e300;
        }
    }
}

// ============================================================
// Kernel 4: decode
// ============================================================
__global__ __launch_bounds__(256)
void decode_kernel(const float* __restrict__ bdec,
                   float* __restrict__ out) {
    const int row = blockIdx.x;
    const int t   = threadIdx.x;
    __shared__ float v[TOPK];
    __shared__ int   id[TOPK];
    if (t < TOPK) { v[t] = g_vals[row * TOPK + t]; id[t] = g_idx[row * TOPK + t]; }
    __syncthreads();

    #pragma unroll
    for (int r = 0; r < 3; ++r) {
        int d = t + r * 256;
        float acc = bdec[d];
        #pragma unroll
        for (int k = 0; k < TOPK; ++k)
            acc += v[k] * g_WdecT[(size_t)id[k] * DMODEL + d];
        out[(size_t)row * DMODEL + d] = acc;
    }
}

// ============================================================
extern "C" void kernel_launch(void* const* d_in, const int* in_sizes, int n_in,
                              void* d_out, int out_size) {
    const float* x     = (const float*)d_in[0];
    const float* W_enc = (const float*)d_in[1];
    const float* b_enc = (const float*)d_in[2];
    const float* W_dec = (const float*)d_in[3];
    const float* b_dec = (const float*)d_in[4];
    float* out = (float*)d_out;

    cudaFuncSetAttribute(encode_gemm, cudaFuncAttributeMaxDynamicSharedMemorySize, GEMM_SMEM);

    size_t npairs = ((size_t)N_ROWS * DMODEL + (size_t)DLATENT * DMODEL) / 2;
    convert_bf16<<<(unsigned)((npairs + 255) / 256), 256>>>(x, W_enc);
    transpose_wdec<<<dim3(DLATENT / 32, DMODEL / 32), dim3(32, 8)>>>(W_dec);
    encode_gemm<<<dim3(DLATENT / BN, N_ROWS / BM), 256, GEMM_SMEM>>>(b_enc);
    topk_cand_kernel<<<N_ROWS, 256>>>();
    refine_kernel<<<N_ROWS, 256>>>(x, W_enc, b_enc);
    decode_kernel<<<N_ROWS, 256>>>(b_dec, out);
}